// round 13
// baseline (speedup 1.0000x reference)
#include <cuda_runtime.h>
#include <cuda_fp16.h>
#include <math.h>

#define NN  50000
#define NE  800000
#define H   96
#define IND 256

typedef unsigned long long ull;

// Scratch (__device__ globals per allocation rules)
// g_qh row m (192 halves): entry j (uint2): .x = q half2 (cols 2j,2j+1),
//                                           .y = hd half2 (cols 2j,2j+1)
__device__ __half g_qh[(size_t)NN * 2 * H];
__device__ __half g_p [(size_t)NN * H];       // (h@Wgd^T + b_gate)/sqrt(192)
__device__ float  g_y [(size_t)NN * 2];       // logits accumulator

__device__ __forceinline__ float tanh_fast(float x) {
    float r;
    asm("tanh.approx.f32 %0, %1;" : "=f"(r) : "f"(x));
    return r;
}
__device__ __forceinline__ ull dup2(float x) {
    ull r;
    asm("mov.b64 %0, {%1, %1};" : "=l"(r) : "f"(x));
    return r;
}
__device__ __forceinline__ ull fma2(ull a, ull b, ull c) {
    ull d;
    asm("fma.rn.f32x2 %0, %1, %2, %3;" : "=l"(d) : "l"(a), "l"(b), "l"(c));
    return d;
}
__device__ __forceinline__ float2 upk2(ull v) {
    float2 f;
    asm("mov.b64 {%0, %1}, %2;" : "=f"(f.x), "=f"(f.y) : "l"(v));
    return f;
}

// ---------------------------------------------------------------------------
__global__ void zero_y_kernel(float* __restrict__ y) {
    int i = blockIdx.x * blockDim.x + threadIdx.x;
    if (i < NN * 2) y[i] = 0.f;
}

// ---------------------------------------------------------------------------
// Fused node pipeline, f32x2 inner loops with zero packing movs for A
// (pairs read straight out of smem as ulonglong2) and one dup-mov per B.
// ---------------------------------------------------------------------------
__global__ void __launch_bounds__(256, 4)
fused_gemm(const float* __restrict__ x,      // [NN, 256]
           const float* __restrict__ W_in,   // [96, 256]
           const float* __restrict__ b_in,   // [96]
           const float* __restrict__ dvec,   // [NN]
           const float* __restrict__ Wg,     // [96, 192]
           const float* __restrict__ bgate,  // [96]
           __half* __restrict__ qh_out,
           __half* __restrict__ p_out)
{
    __shared__ __align__(16) float Hs[96][68];   // h tile, [k][m]
    __shared__ __align__(16) float As[16][68];   // x tile, [k][m]
    __shared__ __align__(16) float Bs[32][96];   // weight tile, [k][n]

    const int tid = threadIdx.x;
    const int tx  = tid & 31;      // n: cols tx, tx+32, tx+64
    const int ty  = tid >> 5;      // m: rows ty*8 .. ty*8+7 (4 f32x2 pairs)
    const int m0  = blockIdx.x * 64;
    const float ic = 0.07216878364870322f;   // 1/sqrt(192)

    ull acc0[4], acc1[4], acc2[4];

    // ---------------- Phase 1: h ----------------
#pragma unroll
    for (int r = 0; r < 4; ++r) { acc0[r] = 0ull; acc1[r] = 0ull; acc2[r] = 0ull; }

    for (int k0 = 0; k0 < IND; k0 += 16) {
        {
            int row  = tid >> 2;
            int kseg = (tid & 3) << 2;
            float4 v = make_float4(0.f, 0.f, 0.f, 0.f);
            int gm = m0 + row;
            if (gm < NN)
                v = *(const float4*)(x + (size_t)gm * IND + k0 + kseg);
            As[kseg + 0][row] = v.x;
            As[kseg + 1][row] = v.y;
            As[kseg + 2][row] = v.z;
            As[kseg + 3][row] = v.w;
        }
        for (int i = tid; i < 96 * 16; i += 256) {
            int n = i >> 4, k = i & 15;
            Bs[k][n] = W_in[(size_t)n * IND + k0 + k];
        }
        __syncthreads();

#pragma unroll
        for (int k = 0; k < 16; ++k) {
            const ull bb0 = dup2(Bs[k][tx]);
            const ull bb1 = dup2(Bs[k][tx + 32]);
            const ull bb2 = dup2(Bs[k][tx + 64]);
            const ulonglong2 A01 = *(const ulonglong2*)&As[k][ty * 8];
            const ulonglong2 A23 = *(const ulonglong2*)&As[k][ty * 8 + 4];
            acc0[0] = fma2(A01.x, bb0, acc0[0]);
            acc1[0] = fma2(A01.x, bb1, acc1[0]);
            acc2[0] = fma2(A01.x, bb2, acc2[0]);
            acc0[1] = fma2(A01.y, bb0, acc0[1]);
            acc1[1] = fma2(A01.y, bb1, acc1[1]);
            acc2[1] = fma2(A01.y, bb2, acc2[1]);
            acc0[2] = fma2(A23.x, bb0, acc0[2]);
            acc1[2] = fma2(A23.x, bb1, acc1[2]);
            acc2[2] = fma2(A23.x, bb2, acc2[2]);
            acc0[3] = fma2(A23.y, bb0, acc0[3]);
            acc1[3] = fma2(A23.y, bb1, acc1[3]);
            acc2[3] = fma2(A23.y, bb2, acc2[3]);
        }
        __syncthreads();
    }

    // Phase 1 epilogue: h -> Hs ; hd -> g_qh interleaved fp16
    {
        const float bb0 = b_in[tx], bb1 = b_in[tx + 32], bb2 = b_in[tx + 64];
        // hd position for column c: (c>>1)*4 + 2 + (c&1)
        const int ho0 = ((tx      ) >> 1) * 4 + 2 + (tx & 1);
        const int ho1 = ((tx + 32 ) >> 1) * 4 + 2 + (tx & 1);
        const int ho2 = ((tx + 64 ) >> 1) * 4 + 2 + (tx & 1);
#pragma unroll
        for (int r = 0; r < 4; ++r) {
            float2 f0 = upk2(acc0[r]);
            float2 f1 = upk2(acc1[r]);
            float2 f2 = upk2(acc2[r]);
#pragma unroll
            for (int s = 0; s < 2; ++s) {
                int ml = ty * 8 + 2 * r + s;
                int m  = m0 + ml;
                float h0 = (s ? f0.y : f0.x) + bb0;
                float h1 = (s ? f1.y : f1.x) + bb1;
                float h2 = (s ? f2.y : f2.x) + bb2;
                Hs[tx][ml]      = h0;
                Hs[tx + 32][ml] = h1;
                Hs[tx + 64][ml] = h2;
                if (m < NN) {
                    float dn = __ldg(dvec + m);
                    __half* qr = qh_out + (size_t)m * (2 * H);
                    qr[ho0] = __float2half(h0 * dn);
                    qr[ho1] = __float2half(h1 * dn);
                    qr[ho2] = __float2half(h2 * dn);
                }
            }
        }
    }
    __syncthreads();

    // ---------------- Phase 2: p'' then q'' ----------------
#pragma unroll 1
    for (int half = 0; half < 2; ++half) {
        const int koff = half * H;
#pragma unroll
        for (int r = 0; r < 4; ++r) { acc0[r] = 0ull; acc1[r] = 0ull; acc2[r] = 0ull; }

#pragma unroll 1
        for (int k0 = 0; k0 < H; k0 += 32) {
            for (int i = tid; i < 96 * 32; i += 256) {
                int n = i >> 5, k = i & 31;
                Bs[k][n] = Wg[(size_t)n * (2 * H) + koff + k0 + k];
            }
            __syncthreads();

#pragma unroll
            for (int k = 0; k < 32; ++k) {
                const ull bb0 = dup2(Bs[k][tx]);
                const ull bb1 = dup2(Bs[k][tx + 32]);
                const ull bb2 = dup2(Bs[k][tx + 64]);
                const ulonglong2 A01 = *(const ulonglong2*)&Hs[k0 + k][ty * 8];
                const ulonglong2 A23 = *(const ulonglong2*)&Hs[k0 + k][ty * 8 + 4];
                acc0[0] = fma2(A01.x, bb0, acc0[0]);
                acc1[0] = fma2(A01.x, bb1, acc1[0]);
                acc2[0] = fma2(A01.x, bb2, acc2[0]);
                acc0[1] = fma2(A01.y, bb0, acc0[1]);
                acc1[1] = fma2(A01.y, bb1, acc1[1]);
                acc2[1] = fma2(A01.y, bb2, acc2[1]);
                acc0[2] = fma2(A23.x, bb0, acc0[2]);
                acc1[2] = fma2(A23.x, bb1, acc1[2]);
                acc2[2] = fma2(A23.x, bb2, acc2[2]);
                acc0[3] = fma2(A23.y, bb0, acc0[3]);
                acc1[3] = fma2(A23.y, bb1, acc1[3]);
                acc2[3] = fma2(A23.y, bb2, acc2[3]);
            }
            __syncthreads();
        }

        const float bb0 = half ? 0.f : bgate[tx];
        const float bb1 = half ? 0.f : bgate[tx + 32];
        const float bb2 = half ? 0.f : bgate[tx + 64];
        // q position for column c: (c>>1)*4 + (c&1)
        const int qo0 = ((tx      ) >> 1) * 4 + (tx & 1);
        const int qo1 = ((tx + 32 ) >> 1) * 4 + (tx & 1);
        const int qo2 = ((tx + 64 ) >> 1) * 4 + (tx & 1);
#pragma unroll
        for (int r = 0; r < 4; ++r) {
            float2 f0 = upk2(acc0[r]);
            float2 f1 = upk2(acc1[r]);
            float2 f2 = upk2(acc2[r]);
#pragma unroll
            for (int s = 0; s < 2; ++s) {
                int m = m0 + ty * 8 + 2 * r + s;
                if (m < NN) {
                    float v0 = ((s ? f0.y : f0.x) + bb0) * ic;
                    float v1 = ((s ? f1.y : f1.x) + bb1) * ic;
                    float v2 = ((s ? f2.y : f2.x) + bb2) * ic;
                    if (half) {   // q'' -> interleaved qh
                        __half* qr = qh_out + (size_t)m * (2 * H);
                        qr[qo0] = __float2half(v0);
                        qr[qo1] = __float2half(v1);
                        qr[qo2] = __float2half(v2);
                    } else {      // p'' -> g_p
                        __half* cr = p_out + (size_t)m * H;
                        cr[tx]      = __float2half(v0);
                        cr[tx + 32] = __float2half(v1);
                        cr[tx + 64] = __float2half(v2);
                    }
                }
            }
        }
    }
}

// ---------------------------------------------------------------------------
// Edge kernel: each warp owns 4 edges; 2 gathers per edge (p uint2 + qh uint4).
// a-store is write-through (__stwt) so the 307MB stream never occupies L2.
// ---------------------------------------------------------------------------
__global__ void __launch_bounds__(256)
edge_kernel(const int* __restrict__ src,
            const int* __restrict__ dst,
            const float* __restrict__ Wc,
            float* __restrict__ a_out,
            float* __restrict__ y)
{
    __shared__ __align__(16) float4 sW[48];   // Wc[2,96] as 48 float4
    const int tid = threadIdx.x;
    if (tid < 48) sW[tid] = ((const float4*)Wc)[tid];
    __syncthreads();

    const int warp = blockIdx.x * 8 + (tid >> 5);
    const int lane = tid & 31;
    const int e0   = warp * 4;                 // grid covers NE exactly

    const int4 sv = __ldg((const int4*)src + warp);
    const int4 tv = __ldg((const int4*)dst + warp);
    const int si[4] = {sv.x, sv.y, sv.z, sv.w};
    const int ti[4] = {tv.x, tv.y, tv.z, tv.w};

    float r0[4] = {0.f, 0.f, 0.f, 0.f};
    float r1[4] = {0.f, 0.f, 0.f, 0.f};

    if (lane < 24) {
        uint2 pr[4];
        uint4 qh[4];
#pragma unroll
        for (int i = 0; i < 4; ++i) {
            pr[i] = __ldg((const uint2*)(g_p  + (size_t)ti[i] * H) + lane);
            qh[i] = __ldg((const uint4*)(g_qh + (size_t)si[i] * (2 * H)) + lane);
        }

        const float4 w0 = sW[lane];
        const float4 w1 = sW[24 + lane];

#pragma unroll
        for (int i = 0; i < 4; ++i) {
            const float2 p0 = __half22float2(*(const __half2*)&pr[i].x);
            const float2 p1 = __half22float2(*(const __half2*)&pr[i].y);
            const float2 q0 = __half22float2(*(const __half2*)&qh[i].x);
            const float2 h0 = __half22float2(*(const __half2*)&qh[i].y);
            const float2 q1 = __half22float2(*(const __half2*)&qh[i].z);
            const float2 h1 = __half22float2(*(const __half2*)&qh[i].w);

            float4 av;
            av.x = tanh_fast(p0.x + q0.x);
            av.y = tanh_fast(p0.y + q0.y);
            av.z = tanh_fast(p1.x + q1.x);
            av.w = tanh_fast(p1.y + q1.y);

            __stwt(((float4*)a_out) + (size_t)(e0 + i) * 24 + lane, av);

            const float4 mv = make_float4(av.x * h0.x, av.y * h0.y,
                                          av.z * h1.x, av.w * h1.y);
            r0[i] = mv.x * w0.x + mv.y * w0.y + mv.z * w0.z + mv.w * w0.w;
            r1[i] = mv.x * w1.x + mv.y * w1.y + mv.z * w1.z + mv.w * w1.w;
        }
    }

#pragma unroll
    for (int o = 16; o; o >>= 1) {
#pragma unroll
        for (int i = 0; i < 4; ++i) {
            r0[i] += __shfl_xor_sync(0xffffffffu, r0[i], o);
            r1[i] += __shfl_xor_sync(0xffffffffu, r1[i], o);
        }
    }

    if (lane < 4) {
        float v0, v1;
        switch (lane) {
            case 0: v0 = r0[0]; v1 = r1[0]; break;
            case 1: v0 = r0[1]; v1 = r1[1]; break;
            case 2: v0 = r0[2]; v1 = r1[2]; break;
            default: v0 = r0[3]; v1 = r1[3]; break;
        }
        float* yp = y + (size_t)ti[lane] * 2;
        asm volatile("red.global.add.v2.f32 [%0], {%1, %2};"
                     :: "l"(yp), "f"(v0), "f"(v1) : "memory");
    }
}

// ---------------------------------------------------------------------------
__global__ void clf_kernel(const float* __restrict__ y,
                           const float* __restrict__ dvec,
                           const float* __restrict__ bc,
                           float* __restrict__ out)
{
    int n = blockIdx.x * blockDim.x + threadIdx.x;
    if (n >= NN) return;
    float dn = dvec[n];
    float y0 = dn * y[2 * n]     + bc[0];
    float y1 = dn * y[2 * n + 1] + bc[1];
    float m  = fmaxf(y0, y1);
    float lse = m + logf(expf(y0 - m) + expf(y1 - m));
    out[2 * n]     = y0 - lse;
    out[2 * n + 1] = y1 - lse;
}

// ---------------------------------------------------------------------------
extern "C" void kernel_launch(void* const* d_in, const int* in_sizes, int n_in,
                              void* d_out, int out_size)
{
    const float* x      = (const float*)d_in[0];
    const float* d      = (const float*)d_in[1];
    const int*   src    = (const int*)  d_in[2];
    const int*   dst    = (const int*)  d_in[3];
    const float* W_in   = (const float*)d_in[4];
    const float* b_in   = (const float*)d_in[5];
    const float* W_gate = (const float*)d_in[6];
    const float* b_gate = (const float*)d_in[7];
    const float* W_clf  = (const float*)d_in[8];
    const float* b_clf  = (const float*)d_in[9];
    float* out = (float*)d_out;

    float  *yp;
    __half *qhp, *pp;
    cudaGetSymbolAddress((void**)&qhp, g_qh);
    cudaGetSymbolAddress((void**)&pp,  g_p);
    cudaGetSymbolAddress((void**)&yp,  g_y);

    zero_y_kernel<<<(NN * 2 + 255) / 256, 256>>>(yp);

    // h, hd, p'', q'' in one kernel (h never touches global memory)
    fused_gemm<<<(NN + 63) / 64, 256>>>(x, W_in, b_in, d, W_gate, b_gate,
                                        qhp, pp);

    // edges: a (tuple order: z first, then a) + logits scatter
    edge_kernel<<<NE / 32, 256>>>(src, dst, W_clf, out + 2 * NN, yp);

    clf_kernel<<<(NN + 255) / 256, 256>>>(yp, d, b_clf, out);
}

// round 14
// speedup vs baseline: 1.0236x; 1.0236x over previous
#include <cuda_runtime.h>
#include <cuda_fp16.h>
#include <math.h>

#define NN  50000
#define NE  800000
#define H   96
#define IND 256

typedef unsigned long long ull;

// Scratch (__device__ globals per allocation rules)
// g_qh row m (192 halves): entry j (uint2): .x = q half2 (cols 2j,2j+1),
//                                           .y = hd half2 (cols 2j,2j+1)
__device__ __half g_qh[(size_t)NN * 2 * H];
__device__ __half g_p [(size_t)NN * H];       // (h@Wgd^T + b_gate)/sqrt(192)
__device__ float  g_y [(size_t)NN * 2];       // logits accumulator

__device__ __forceinline__ float tanh_fast(float x) {
    float r;
    asm("tanh.approx.f32 %0, %1;" : "=f"(r) : "f"(x));
    return r;
}
__device__ __forceinline__ ull dup2(float x) {
    ull r;
    asm("mov.b64 %0, {%1, %1};" : "=l"(r) : "f"(x));
    return r;
}
__device__ __forceinline__ ull fma2(ull a, ull b, ull c) {
    ull d;
    asm("fma.rn.f32x2 %0, %1, %2, %3;" : "=l"(d) : "l"(a), "l"(b), "l"(c));
    return d;
}
__device__ __forceinline__ float2 upk2(ull v) {
    float2 f;
    asm("mov.b64 {%0, %1}, %2;" : "=f"(f.x), "=f"(f.y) : "l"(v));
    return f;
}

// ---------------------------------------------------------------------------
__global__ void zero_y_kernel(float* __restrict__ y) {
    int i = blockIdx.x * blockDim.x + threadIdx.x;
    if (i < NN * 2) y[i] = 0.f;
}

// ---------------------------------------------------------------------------
// Fused node pipeline, f32x2 inner loops, SOFTWARE-PIPELINED global loads:
// each tile's LDGs are issued during the previous tile's compute block.
// ---------------------------------------------------------------------------
__global__ void __launch_bounds__(256, 3)
fused_gemm(const float* __restrict__ x,      // [NN, 256]
           const float* __restrict__ W_in,   // [96, 256]
           const float* __restrict__ b_in,   // [96]
           const float* __restrict__ dvec,   // [NN]
           const float* __restrict__ Wg,     // [96, 192]
           const float* __restrict__ bgate,  // [96]
           __half* __restrict__ qh_out,
           __half* __restrict__ p_out)
{
    __shared__ __align__(16) float Hs[96][68];   // h tile, [k][m]
    __shared__ __align__(16) float As[16][68];   // x tile, [k][m]
    __shared__ __align__(16) float Bs[32][96];   // weight tile, [k][n]

    const int tid = threadIdx.x;
    const int tx  = tid & 31;      // n: cols tx, tx+32, tx+64
    const int ty  = tid >> 5;      // m: rows ty*8 .. ty*8+7 (4 f32x2 pairs)
    const int m0  = blockIdx.x * 64;
    const float ic = 0.07216878364870322f;   // 1/sqrt(192)

    ull acc0[4], acc1[4], acc2[4];

    const int arow = tid >> 2;            // 0..63
    const int kseg = (tid & 3) << 2;      // 0,4,8,12
    const int agm  = m0 + arow;

    // ---------------- Phase 1: h (K=256, BK=16, 16 tiles) ----------------
    float4 pa;
    float  pb[6];
    // prefetch tile 0
    pa = (agm < NN) ? *(const float4*)(x + (size_t)agm * IND + kseg)
                    : make_float4(0.f, 0.f, 0.f, 0.f);
#pragma unroll
    for (int j = 0; j < 6; ++j) {
        int i = tid + j * 256;
        pb[j] = W_in[(size_t)(i >> 4) * IND + (i & 15)];
    }

#pragma unroll
    for (int r = 0; r < 4; ++r) { acc0[r] = 0ull; acc1[r] = 0ull; acc2[r] = 0ull; }

#pragma unroll 1
    for (int t = 0; t < 16; ++t) {
        // commit prefetched tile to smem
        As[kseg + 0][arow] = pa.x;
        As[kseg + 1][arow] = pa.y;
        As[kseg + 2][arow] = pa.z;
        As[kseg + 3][arow] = pa.w;
#pragma unroll
        for (int j = 0; j < 6; ++j) {
            int i = tid + j * 256;
            Bs[i & 15][i >> 4] = pb[j];
        }
        __syncthreads();

        // issue next tile's LDGs (overlap with compute below)
        if (t < 15) {
            const int k0 = (t + 1) * 16;
            pa = (agm < NN) ? *(const float4*)(x + (size_t)agm * IND + k0 + kseg)
                            : make_float4(0.f, 0.f, 0.f, 0.f);
#pragma unroll
            for (int j = 0; j < 6; ++j) {
                int i = tid + j * 256;
                pb[j] = W_in[(size_t)(i >> 4) * IND + k0 + (i & 15)];
            }
        }

#pragma unroll
        for (int k = 0; k < 16; ++k) {
            const ull bb0 = dup2(Bs[k][tx]);
            const ull bb1 = dup2(Bs[k][tx + 32]);
            const ull bb2 = dup2(Bs[k][tx + 64]);
            const ulonglong2 A01 = *(const ulonglong2*)&As[k][ty * 8];
            const ulonglong2 A23 = *(const ulonglong2*)&As[k][ty * 8 + 4];
            acc0[0] = fma2(A01.x, bb0, acc0[0]);
            acc1[0] = fma2(A01.x, bb1, acc1[0]);
            acc2[0] = fma2(A01.x, bb2, acc2[0]);
            acc0[1] = fma2(A01.y, bb0, acc0[1]);
            acc1[1] = fma2(A01.y, bb1, acc1[1]);
            acc2[1] = fma2(A01.y, bb2, acc2[1]);
            acc0[2] = fma2(A23.x, bb0, acc0[2]);
            acc1[2] = fma2(A23.x, bb1, acc1[2]);
            acc2[2] = fma2(A23.x, bb2, acc2[2]);
            acc0[3] = fma2(A23.y, bb0, acc0[3]);
            acc1[3] = fma2(A23.y, bb1, acc1[3]);
            acc2[3] = fma2(A23.y, bb2, acc2[3]);
        }
        __syncthreads();
    }

    // prefetch phase-2 tile 0 (overlaps with phase-1 epilogue)
    float pw[12];
#pragma unroll
    for (int j = 0; j < 12; ++j) {
        int i = tid + j * 256;
        pw[j] = Wg[(size_t)(i >> 5) * (2 * H) + (i & 31)];
    }

    // Phase 1 epilogue: h -> Hs ; hd -> g_qh interleaved fp16
    {
        const float bb0 = b_in[tx], bb1 = b_in[tx + 32], bb2 = b_in[tx + 64];
        // hd position for column c: (c>>1)*4 + 2 + (c&1)
        const int ho0 = ((tx      ) >> 1) * 4 + 2 + (tx & 1);
        const int ho1 = ((tx + 32 ) >> 1) * 4 + 2 + (tx & 1);
        const int ho2 = ((tx + 64 ) >> 1) * 4 + 2 + (tx & 1);
#pragma unroll
        for (int r = 0; r < 4; ++r) {
            float2 f0 = upk2(acc0[r]);
            float2 f1 = upk2(acc1[r]);
            float2 f2 = upk2(acc2[r]);
#pragma unroll
            for (int s = 0; s < 2; ++s) {
                int ml = ty * 8 + 2 * r + s;
                int m  = m0 + ml;
                float h0 = (s ? f0.y : f0.x) + bb0;
                float h1 = (s ? f1.y : f1.x) + bb1;
                float h2 = (s ? f2.y : f2.x) + bb2;
                Hs[tx][ml]      = h0;
                Hs[tx + 32][ml] = h1;
                Hs[tx + 64][ml] = h2;
                if (m < NN) {
                    float dn = __ldg(dvec + m);
                    __half* qr = qh_out + (size_t)m * (2 * H);
                    qr[ho0] = __float2half(h0 * dn);
                    qr[ho1] = __float2half(h1 * dn);
                    qr[ho2] = __float2half(h2 * dn);
                }
            }
        }
    }
    __syncthreads();

    // ---------------- Phase 2: 6 tiles (p'' tiles 0-2, q'' tiles 3-5) -----
#pragma unroll 1
    for (int tile = 0; tile < 6; ++tile) {
        const int hf = (tile >= 3) ? 1 : 0;
        const int kt = tile - 3 * hf;

        // commit prefetched Wg tile to smem
#pragma unroll
        for (int j = 0; j < 12; ++j) {
            int i = tid + j * 256;
            Bs[i & 31][i >> 5] = pw[j];
        }
        __syncthreads();

        // issue next tile's LDGs
        if (tile < 5) {
            const int nt  = tile + 1;
            const int nhf = (nt >= 3) ? 1 : 0;
            const int nk0 = nhf * H + (nt - 3 * nhf) * 32;
#pragma unroll
            for (int j = 0; j < 12; ++j) {
                int i = tid + j * 256;
                pw[j] = Wg[(size_t)(i >> 5) * (2 * H) + nk0 + (i & 31)];
            }
        }

        if (kt == 0) {
#pragma unroll
            for (int r = 0; r < 4; ++r) { acc0[r] = 0ull; acc1[r] = 0ull; acc2[r] = 0ull; }
        }

        const int kb = kt * 32;
#pragma unroll
        for (int k = 0; k < 32; ++k) {
            const ull bb0 = dup2(Bs[k][tx]);
            const ull bb1 = dup2(Bs[k][tx + 32]);
            const ull bb2 = dup2(Bs[k][tx + 64]);
            const ulonglong2 A01 = *(const ulonglong2*)&Hs[kb + k][ty * 8];
            const ulonglong2 A23 = *(const ulonglong2*)&Hs[kb + k][ty * 8 + 4];
            acc0[0] = fma2(A01.x, bb0, acc0[0]);
            acc1[0] = fma2(A01.x, bb1, acc1[0]);
            acc2[0] = fma2(A01.x, bb2, acc2[0]);
            acc0[1] = fma2(A01.y, bb0, acc0[1]);
            acc1[1] = fma2(A01.y, bb1, acc1[1]);
            acc2[1] = fma2(A01.y, bb2, acc2[1]);
            acc0[2] = fma2(A23.x, bb0, acc0[2]);
            acc1[2] = fma2(A23.x, bb1, acc1[2]);
            acc2[2] = fma2(A23.x, bb2, acc2[2]);
            acc0[3] = fma2(A23.y, bb0, acc0[3]);
            acc1[3] = fma2(A23.y, bb1, acc1[3]);
            acc2[3] = fma2(A23.y, bb2, acc2[3]);
        }
        __syncthreads();

        if (kt == 2) {
            const float bb0 = hf ? 0.f : bgate[tx];
            const float bb1 = hf ? 0.f : bgate[tx + 32];
            const float bb2 = hf ? 0.f : bgate[tx + 64];
            // q position for column c: (c>>1)*4 + (c&1)
            const int qo0 = ((tx      ) >> 1) * 4 + (tx & 1);
            const int qo1 = ((tx + 32 ) >> 1) * 4 + (tx & 1);
            const int qo2 = ((tx + 64 ) >> 1) * 4 + (tx & 1);
#pragma unroll
            for (int r = 0; r < 4; ++r) {
                float2 f0 = upk2(acc0[r]);
                float2 f1 = upk2(acc1[r]);
                float2 f2 = upk2(acc2[r]);
#pragma unroll
                for (int s = 0; s < 2; ++s) {
                    int m = m0 + ty * 8 + 2 * r + s;
                    if (m < NN) {
                        float v0 = ((s ? f0.y : f0.x) + bb0) * ic;
                        float v1 = ((s ? f1.y : f1.x) + bb1) * ic;
                        float v2 = ((s ? f2.y : f2.x) + bb2) * ic;
                        if (hf) {   // q'' -> interleaved qh
                            __half* qr = qh_out + (size_t)m * (2 * H);
                            qr[qo0] = __float2half(v0);
                            qr[qo1] = __float2half(v1);
                            qr[qo2] = __float2half(v2);
                        } else {    // p'' -> g_p
                            __half* cr = p_out + (size_t)m * H;
                            cr[tx]      = __float2half(v0);
                            cr[tx + 32] = __float2half(v1);
                            cr[tx + 64] = __float2half(v2);
                        }
                    }
                }
            }
        }
    }
}

// ---------------------------------------------------------------------------
// Edge kernel: each warp owns 4 edges; 2 gathers per edge (p uint2 + qh uint4).
// ---------------------------------------------------------------------------
__global__ void __launch_bounds__(256)
edge_kernel(const int* __restrict__ src,
            const int* __restrict__ dst,
            const float* __restrict__ Wc,
            float* __restrict__ a_out,
            float* __restrict__ y)
{
    __shared__ __align__(16) float4 sW[48];   // Wc[2,96] as 48 float4
    const int tid = threadIdx.x;
    if (tid < 48) sW[tid] = ((const float4*)Wc)[tid];
    __syncthreads();

    const int warp = blockIdx.x * 8 + (tid >> 5);
    const int lane = tid & 31;
    const int e0   = warp * 4;                 // grid covers NE exactly

    const int4 sv = __ldg((const int4*)src + warp);
    const int4 tv = __ldg((const int4*)dst + warp);
    const int si[4] = {sv.x, sv.y, sv.z, sv.w};
    const int ti[4] = {tv.x, tv.y, tv.z, tv.w};

    float r0[4] = {0.f, 0.f, 0.f, 0.f};
    float r1[4] = {0.f, 0.f, 0.f, 0.f};

    if (lane < 24) {
        uint2 pr[4];
        uint4 qh[4];
#pragma unroll
        for (int i = 0; i < 4; ++i) {
            pr[i] = __ldg((const uint2*)(g_p  + (size_t)ti[i] * H) + lane);
            qh[i] = __ldg((const uint4*)(g_qh + (size_t)si[i] * (2 * H)) + lane);
        }

        const float4 w0 = sW[lane];
        const float4 w1 = sW[24 + lane];

#pragma unroll
        for (int i = 0; i < 4; ++i) {
            const float2 p0 = __half22float2(*(const __half2*)&pr[i].x);
            const float2 p1 = __half22float2(*(const __half2*)&pr[i].y);
            const float2 q0 = __half22float2(*(const __half2*)&qh[i].x);
            const float2 h0 = __half22float2(*(const __half2*)&qh[i].y);
            const float2 q1 = __half22float2(*(const __half2*)&qh[i].z);
            const float2 h1 = __half22float2(*(const __half2*)&qh[i].w);

            float4 av;
            av.x = tanh_fast(p0.x + q0.x);
            av.y = tanh_fast(p0.y + q0.y);
            av.z = tanh_fast(p1.x + q1.x);
            av.w = tanh_fast(p1.y + q1.y);

            __stcs(((float4*)a_out) + (size_t)(e0 + i) * 24 + lane, av);

            const float4 mv = make_float4(av.x * h0.x, av.y * h0.y,
                                          av.z * h1.x, av.w * h1.y);
            r0[i] = mv.x * w0.x + mv.y * w0.y + mv.z * w0.z + mv.w * w0.w;
            r1[i] = mv.x * w1.x + mv.y * w1.y + mv.z * w1.z + mv.w * w1.w;
        }
    }

#pragma unroll
    for (int o = 16; o; o >>= 1) {
#pragma unroll
        for (int i = 0; i < 4; ++i) {
            r0[i] += __shfl_xor_sync(0xffffffffu, r0[i], o);
            r1[i] += __shfl_xor_sync(0xffffffffu, r1[i], o);
        }
    }

    if (lane < 4) {
        float v0, v1;
        switch (lane) {
            case 0: v0 = r0[0]; v1 = r1[0]; break;
            case 1: v0 = r0[1]; v1 = r1[1]; break;
            case 2: v0 = r0[2]; v1 = r1[2]; break;
            default: v0 = r0[3]; v1 = r1[3]; break;
        }
        float* yp = y + (size_t)ti[lane] * 2;
        asm volatile("red.global.add.v2.f32 [%0], {%1, %2};"
                     :: "l"(yp), "f"(v0), "f"(v1) : "memory");
    }
}

// ---------------------------------------------------------------------------
__global__ void clf_kernel(const float* __restrict__ y,
                           const float* __restrict__ dvec,
                           const float* __restrict__ bc,
                           float* __restrict__ out)
{
    int n = blockIdx.x * blockDim.x + threadIdx.x;
    if (n >= NN) return;
    float dn = dvec[n];
    float y0 = dn * y[2 * n]     + bc[0];
    float y1 = dn * y[2 * n + 1] + bc[1];
    float m  = fmaxf(y0, y1);
    float lse = m + logf(expf(y0 - m) + expf(y1 - m));
    out[2 * n]     = y0 - lse;
    out[2 * n + 1] = y1 - lse;
}

// ---------------------------------------------------------------------------
extern "C" void kernel_launch(void* const* d_in, const int* in_sizes, int n_in,
                              void* d_out, int out_size)
{
    const float* x      = (const float*)d_in[0];
    const float* d      = (const float*)d_in[1];
    const int*   src    = (const int*)  d_in[2];
    const int*   dst    = (const int*)  d_in[3];
    const float* W_in   = (const float*)d_in[4];
    const float* b_in   = (const float*)d_in[5];
    const float* W_gate = (const float*)d_in[6];
    const float* b_gate = (const float*)d_in[7];
    const float* W_clf  = (const float*)d_in[8];
    const float* b_clf  = (const float*)d_in[9];
    float* out = (float*)d_out;

    float  *yp;
    __half *qhp, *pp;
    cudaGetSymbolAddress((void**)&qhp, g_qh);
    cudaGetSymbolAddress((void**)&pp,  g_p);
    cudaGetSymbolAddress((void**)&yp,  g_y);

    zero_y_kernel<<<(NN * 2 + 255) / 256, 256>>>(yp);

    // h, hd, p'', q'' in one kernel (h never touches global memory)
    fused_gemm<<<(NN + 63) / 64, 256>>>(x, W_in, b_in, d, W_gate, b_gate,
                                        qhp, pp);

    // edges: a (tuple order: z first, then a) + logits scatter
    edge_kernel<<<NE / 32, 256>>>(src, dst, W_clf, out + 2 * NN, yp);

    clf_kernel<<<(NN + 255) / 256, 256>>>(yp, d, b_clf, out);
}